// round 4
// baseline (speedup 1.0000x reference)
#include <cuda_runtime.h>
#include <cuda_bf16.h>
#include <cstdint>

#define NWIN   2048
#define WIN    64
#define DIM    256
#define HEADS  8
#define HD     32
#define QKV_N  768
#define MROWS  (NWIN*WIN)  // 131072

__device__ float g_q[(size_t)NWIN*HEADS*WIN*HD];
__device__ float g_k[(size_t)NWIN*HEADS*WIN*HD];
__device__ float g_v[(size_t)NWIN*HEADS*WIN*HD];
__device__ float g_ao[(size_t)NWIN*WIN*DIM];
__device__ float g_bias[HEADS*WIN*WIN];   // precomputed rel-pos bias per head

__device__ __forceinline__ unsigned f2tf32(float f) {
    unsigned r;
    asm("cvt.rna.tf32.f32 %0, %1;" : "=r"(r) : "f"(f));
    return r;
}

__device__ __forceinline__ void mma_tf32(float c[4],
                                         unsigned a0, unsigned a1, unsigned a2, unsigned a3,
                                         unsigned b0, unsigned b1) {
    asm volatile(
        "mma.sync.aligned.m16n8k8.row.col.f32.tf32.tf32.f32 "
        "{%0,%1,%2,%3}, {%4,%5,%6,%7}, {%8,%9}, {%0,%1,%2,%3};"
        : "+f"(c[0]), "+f"(c[1]), "+f"(c[2]), "+f"(c[3])
        : "r"(a0), "r"(a1), "r"(a2), "r"(a3), "r"(b0), "r"(b1));
}

// ---------------------------------------------------------------------------
// GEMM: C[Mx N] = A[MxK] @ W[NxK]^T + bias, K=256. Block 128x128, 4 warps,
// warp 64x64. BK=16, 2-stage smem pipeline with register prefetch.
// ---------------------------------------------------------------------------
#define GP 20   // smem pitch (words): (20g+tg) mod 32 covers all banks

template<bool QKV>
__global__ void __launch_bounds__(128, 2) mma_gemm(const float* __restrict__ A,
                                                   const float* __restrict__ W,
                                                   const float* __restrict__ bias,
                                                   float* __restrict__ out)
{
    __shared__ unsigned As[2][128 * GP];
    __shared__ unsigned Bs[2][128 * GP];

    const int rowBase = blockIdx.y * 128;
    const int colBase = blockIdx.x * 128;
    const int tid  = threadIdx.x;
    const int lane = tid & 31;
    const int warp = tid >> 5;
    const int warpM = warp >> 1, warpN = warp & 1;
    const int g  = lane >> 2, tg = lane & 3;
    const int m0 = warpM * 64, n0 = warpN * 64;

    const int lr = tid >> 2;          // base row (stride 32 per i)
    const int lc = (tid & 3) * 4;     // col within 16-wide tile

    float4 va[4], vb[4];
    #pragma unroll
    for (int i = 0; i < 4; i++) {
        const int r = lr + 32 * i;
        va[i] = *(const float4*)&A[(size_t)(rowBase + r) * DIM + lc];
        vb[i] = *(const float4*)&W[(size_t)(colBase + r) * DIM + lc];
    }
    #pragma unroll
    for (int i = 0; i < 4; i++) {
        const int r = lr + 32 * i;
        *(uint4*)&As[0][r * GP + lc] =
            make_uint4(f2tf32(va[i].x), f2tf32(va[i].y), f2tf32(va[i].z), f2tf32(va[i].w));
        *(uint4*)&Bs[0][r * GP + lc] =
            make_uint4(f2tf32(vb[i].x), f2tf32(vb[i].y), f2tf32(vb[i].z), f2tf32(vb[i].w));
    }
    __syncthreads();

    float acc[4][8][4] = {};

    for (int it = 0; it < 16; it++) {
        if (it < 15) {
            const int kb = (it + 1) * 16;
            #pragma unroll
            for (int i = 0; i < 4; i++) {
                const int r = lr + 32 * i;
                va[i] = *(const float4*)&A[(size_t)(rowBase + r) * DIM + kb + lc];
                vb[i] = *(const float4*)&W[(size_t)(colBase + r) * DIM + kb + lc];
            }
        }
        const unsigned* as = As[it & 1];
        const unsigned* bs = Bs[it & 1];
        #pragma unroll
        for (int ks = 0; ks < 2; ks++) {
            const int k0 = ks * 8;
            unsigned af[4][4];
            #pragma unroll
            for (int am = 0; am < 4; am++) {
                const int mr = m0 + am * 16;
                af[am][0] = as[(mr + g)     * GP + k0 + tg];
                af[am][1] = as[(mr + g + 8) * GP + k0 + tg];
                af[am][2] = as[(mr + g)     * GP + k0 + tg + 4];
                af[am][3] = as[(mr + g + 8) * GP + k0 + tg + 4];
            }
            unsigned bf[8][2];
            #pragma unroll
            for (int an = 0; an < 8; an++) {
                const int nr = n0 + an * 8;
                bf[an][0] = bs[(nr + g) * GP + k0 + tg];
                bf[an][1] = bs[(nr + g) * GP + k0 + tg + 4];
            }
            #pragma unroll
            for (int am = 0; am < 4; am++)
                #pragma unroll
                for (int an = 0; an < 8; an++)
                    mma_tf32(acc[am][an], af[am][0], af[am][1], af[am][2], af[am][3],
                             bf[an][0], bf[an][1]);
        }
        if (it < 15) {
            const int s = (it + 1) & 1;
            #pragma unroll
            for (int i = 0; i < 4; i++) {
                const int r = lr + 32 * i;
                *(uint4*)&As[s][r * GP + lc] =
                    make_uint4(f2tf32(va[i].x), f2tf32(va[i].y), f2tf32(va[i].z), f2tf32(va[i].w));
                *(uint4*)&Bs[s][r * GP + lc] =
                    make_uint4(f2tf32(vb[i].x), f2tf32(vb[i].y), f2tf32(vb[i].z), f2tf32(vb[i].w));
            }
        }
        __syncthreads();
    }

    // Epilogue
    #pragma unroll
    for (int am = 0; am < 4; am++) {
        #pragma unroll
        for (int an = 0; an < 8; an++) {
            const int col = colBase + n0 + an * 8 + 2 * tg;
            const float bi0 = bias[col], bi1 = bias[col + 1];
            #pragma unroll
            for (int half = 0; half < 2; half++) {
                const int row = rowBase + m0 + am * 16 + g + 8 * half;
                float2 v;
                v.x = acc[am][an][2 * half]     + bi0;
                v.y = acc[am][an][2 * half + 1] + bi1;
                if (QKV) {
                    const int b = row >> 6, n = row & 63;
                    const int which = col >> 8;
                    const int h = (col >> 5) & 7;
                    const int d = col & 31;
                    float* dst = (which == 0) ? g_q : (which == 1) ? g_k : g_v;
                    *(float2*)&dst[((((size_t)b * HEADS + h) * WIN) + n) * HD + d] = v;
                } else {
                    *(float2*)&out[(size_t)row * DIM + col] = v;
                }
            }
        }
    }
}

// ---------------------------------------------------------------------------
// Precompute rel-pos bias per head: g_bias[h*4096 + e] = bt[rpi[e]*8 + h]
// ---------------------------------------------------------------------------
__global__ void bias_pre(const float* __restrict__ bt, const int* __restrict__ rpi)
{
    const int idx = blockIdx.x * 256 + threadIdx.x;   // 0..32767
    const int h = idx >> 12, e = idx & 4095;
    g_bias[idx] = bt[rpi[e] * HEADS + h];
}

// ---------------------------------------------------------------------------
// Attention with 3xTF32 tensor-core MMA. One block per (window,head), 128 thr.
// smem (floats): qh[64*36] ql kh kl vh[64*40] vl ; at[64*68]/plo alias q/k.
// ---------------------------------------------------------------------------
#define AP 36
#define VP 40
#define PP 68
#define SQH 0
#define SQL 2304
#define SKH 4608
#define SKL 6912
#define SVH 9216
#define SVL 11776
#define SAT 0        // alias over qh+ql (needs 4352 <= 4608)
#define SPL 4608     // alias over kh+kl (needs 4352 <= 4608)
#define ATTN_SMEM_FLOATS 14336
#define ATTN_SMEM_BYTES  (ATTN_SMEM_FLOATS * 4)

__device__ __forceinline__ unsigned fbits(float x) { return __float_as_uint(x); }

__global__ void __launch_bounds__(128) attn_kernel(const float* __restrict__ mask,
                                                   const float* __restrict__ logit_scale)
{
    extern __shared__ float sm[];
    const int bh = blockIdx.x;
    const int b  = bh >> 3;
    const int h  = bh & 7;
    const int tid  = threadIdx.x;
    const int lane = tid & 31;
    const int warp = tid >> 5;
    const int g  = lane >> 2, tg = lane & 3;
    const int m0 = warp * 16;

    // Phase 0: load q,k,v fp32
    const size_t base = (size_t)bh * WIN * HD;
    #pragma unroll
    for (int i = 0; i < 4; i++) {
        const int idx = tid + 128 * i;        // 0..511
        const int n = idx >> 3, c = (idx & 7) * 4;
        *(float4*)&sm[SQH + n * AP + c] = *(const float4*)&g_q[base + n * HD + c];
        *(float4*)&sm[SKH + n * AP + c] = *(const float4*)&g_k[base + n * HD + c];
        *(float4*)&sm[SVH + n * VP + c] = *(const float4*)&g_v[base + n * HD + c];
    }
    __syncthreads();

    // Phase 1: normalize q (with scale) / k, split to tf32 hi/lo; v hi/lo split
    {
        const float ls = __expf(fminf(logit_scale[h], 4.6051701859880914f));
        float* rowp = (tid < 64) ? &sm[SQH + tid * AP] : &sm[SKH + (tid - 64) * AP];
        float* lop  = (tid < 64) ? &sm[SQL + tid * AP] : &sm[SKL + (tid - 64) * AP];
        float s = 0.f;
        #pragma unroll
        for (int d = 0; d < HD; d++) s += rowp[d] * rowp[d];
        float inv = 1.0f / fmaxf(sqrtf(s), 1e-12f);
        if (tid < 64) inv *= ls;
        #pragma unroll
        for (int d = 0; d < HD; d++) {
            const float x = rowp[d] * inv;
            const float hf = __uint_as_float(f2tf32(x));
            rowp[d] = hf;
            lop[d] = __uint_as_float(f2tf32(x - hf));
        }
        #pragma unroll
        for (int j = 0; j < 16; j++) {
            const int e = tid * 16 + j;
            const int n = e >> 5, d = e & 31;
            const float x = sm[SVH + n * VP + d];
            const float hf = __uint_as_float(f2tf32(x));
            sm[SVH + n * VP + d] = hf;
            sm[SVL + n * VP + d] = __uint_as_float(f2tf32(x - hf));
        }
    }
    __syncthreads();

    // Phase 2: QK^T 3xTF32. warp -> rows m0..m0+15, 8 n-atoms, 4 k-atoms.
    float acc[8][4] = {};
    #pragma unroll
    for (int ka = 0; ka < 4; ka++) {
        const int k0 = ka * 8;
        unsigned ah[4], al[4];
        ah[0] = fbits(sm[SQH + (m0 + g)     * AP + k0 + tg]);
        ah[1] = fbits(sm[SQH + (m0 + g + 8) * AP + k0 + tg]);
        ah[2] = fbits(sm[SQH + (m0 + g)     * AP + k0 + tg + 4]);
        ah[3] = fbits(sm[SQH + (m0 + g + 8) * AP + k0 + tg + 4]);
        al[0] = fbits(sm[SQL + (m0 + g)     * AP + k0 + tg]);
        al[1] = fbits(sm[SQL + (m0 + g + 8) * AP + k0 + tg]);
        al[2] = fbits(sm[SQL + (m0 + g)     * AP + k0 + tg + 4]);
        al[3] = fbits(sm[SQL + (m0 + g + 8) * AP + k0 + tg + 4]);
        #pragma unroll
        for (int an = 0; an < 8; an++) {
            const int nr = an * 8;
            unsigned bh0 = fbits(sm[SKH + (nr + g) * AP + k0 + tg]);
            unsigned bh1 = fbits(sm[SKH + (nr + g) * AP + k0 + tg + 4]);
            unsigned bl0 = fbits(sm[SKL + (nr + g) * AP + k0 + tg]);
            unsigned bl1 = fbits(sm[SKL + (nr + g) * AP + k0 + tg + 4]);
            mma_tf32(acc[an], ah[0], ah[1], ah[2], ah[3], bh0, bh1);
            mma_tf32(acc[an], ah[0], ah[1], ah[2], ah[3], bl0, bl1);
            mma_tf32(acc[an], al[0], al[1], al[2], al[3], bh0, bh1);
        }
    }
    __syncthreads();   // q/k smem reads complete before P-store aliases them

    // Phase 3: bias + mask + softmax, all in registers
    const int r0 = m0 + g, r1 = r0 + 8;
    {
        const float* bi = g_bias + h * 4096;
        const float* mk = mask + (size_t)(b & 255) * 4096;
        float m0v = -1e30f, m1v = -1e30f;
        #pragma unroll
        for (int an = 0; an < 8; an++) {
            const int c = an * 8 + 2 * tg;
            acc[an][0] += bi[r0 * 64 + c]     + mk[r0 * 64 + c];
            acc[an][1] += bi[r0 * 64 + c + 1] + mk[r0 * 64 + c + 1];
            acc[an][2] += bi[r1 * 64 + c]     + mk[r1 * 64 + c];
            acc[an][3] += bi[r1 * 64 + c + 1] + mk[r1 * 64 + c + 1];
            m0v = fmaxf(m0v, fmaxf(acc[an][0], acc[an][1]));
            m1v = fmaxf(m1v, fmaxf(acc[an][2], acc[an][3]));
        }
        m0v = fmaxf(m0v, __shfl_xor_sync(0xffffffffu, m0v, 1));
        m0v = fmaxf(m0v, __shfl_xor_sync(0xffffffffu, m0v, 2));
        m1v = fmaxf(m1v, __shfl_xor_sync(0xffffffffu, m1v, 1));
        m1v = fmaxf(m1v, __shfl_xor_sync(0xffffffffu, m1v, 2));
        float s0 = 0.f, s1 = 0.f;
        #pragma unroll
        for (int an = 0; an < 8; an++) {
            acc[an][0] = __expf(acc[an][0] - m0v); s0 += acc[an][0];
            acc[an][1] = __expf(acc[an][1] - m0v); s0 += acc[an][1];
            acc[an][2] = __expf(acc[an][2] - m1v); s1 += acc[an][2];
            acc[an][3] = __expf(acc[an][3] - m1v); s1 += acc[an][3];
        }
        s0 += __shfl_xor_sync(0xffffffffu, s0, 1);
        s0 += __shfl_xor_sync(0xffffffffu, s0, 2);
        s1 += __shfl_xor_sync(0xffffffffu, s1, 1);
        s1 += __shfl_xor_sync(0xffffffffu, s1, 2);
        const float i0 = 1.0f / s0, i1 = 1.0f / s1;
        #pragma unroll
        for (int an = 0; an < 8; an++) {
            acc[an][0] *= i0; acc[an][1] *= i0;
            acc[an][2] *= i1; acc[an][3] *= i1;
        }
    }

    // Phase 4: store P hi/lo (warp writes only its own 16 rows)
    #pragma unroll
    for (int an = 0; an < 8; an++) {
        const int c = an * 8 + 2 * tg;
        #pragma unroll
        for (int q = 0; q < 4; q++) {
            const int rr = (q < 2) ? r0 : r1;
            const int cc = c + (q & 1);
            const float p = acc[an][q];
            const float hf = __uint_as_float(f2tf32(p));
            sm[SAT + rr * PP + cc] = hf;
            sm[SPL + rr * PP + cc] = __uint_as_float(f2tf32(p - hf));
        }
    }
    __syncwarp();

    // Phase 5: out = P @ V, 3xTF32. rows m0..+15, 4 n-atoms (32 cols), 8 k-atoms.
    float oacc[4][4] = {};
    #pragma unroll
    for (int kj = 0; kj < 8; kj++) {
        const int k0 = kj * 8;
        unsigned ah[4], al[4];
        ah[0] = fbits(sm[SAT + (m0 + g)     * PP + k0 + tg]);
        ah[1] = fbits(sm[SAT + (m0 + g + 8) * PP + k0 + tg]);
        ah[2] = fbits(sm[SAT + (m0 + g)     * PP + k0 + tg + 4]);
        ah[3] = fbits(sm[SAT + (m0 + g + 8) * PP + k0 + tg + 4]);
        al[0] = fbits(sm[SPL + (m0 + g)     * PP + k0 + tg]);
        al[1] = fbits(sm[SPL + (m0 + g + 8) * PP + k0 + tg]);
        al[2] = fbits(sm[SPL + (m0 + g)     * PP + k0 + tg + 4]);
        al[3] = fbits(sm[SPL + (m0 + g + 8) * PP + k0 + tg + 4]);
        #pragma unroll
        for (int dn = 0; dn < 4; dn++) {
            const int nn = dn * 8;
            unsigned bh0 = fbits(sm[SVH + (k0 + tg)     * VP + nn + g]);
            unsigned bh1 = fbits(sm[SVH + (k0 + tg + 4) * VP + nn + g]);
            unsigned bl0 = fbits(sm[SVL + (k0 + tg)     * VP + nn + g]);
            unsigned bl1 = fbits(sm[SVL + (k0 + tg + 4) * VP + nn + g]);
            mma_tf32(oacc[dn], ah[0], ah[1], ah[2], ah[3], bh0, bh1);
            mma_tf32(oacc[dn], ah[0], ah[1], ah[2], ah[3], bl0, bl1);
            mma_tf32(oacc[dn], al[0], al[1], al[2], al[3], bh0, bh1);
        }
    }

    float* aop = g_ao + (size_t)b * WIN * DIM + h * HD;
    #pragma unroll
    for (int dn = 0; dn < 4; dn++) {
        const int c = dn * 8 + 2 * tg;
        float2 v0 = make_float2(oacc[dn][0], oacc[dn][1]);
        float2 v1 = make_float2(oacc[dn][2], oacc[dn][3]);
        *(float2*)&aop[(size_t)r0 * DIM + c] = v0;
        *(float2*)&aop[(size_t)r1 * DIM + c] = v1;
    }
}

// ---------------------------------------------------------------------------
extern "C" void kernel_launch(void* const* d_in, const int* in_sizes, int n_in,
                              void* d_out, int out_size)
{
    const float* x        = (const float*)d_in[0];
    const float* mask     = (const float*)d_in[1];
    const float* qkv_w    = (const float*)d_in[2];
    const float* qkv_b    = (const float*)d_in[3];
    const float* proj_w   = (const float*)d_in[4];
    const float* proj_b   = (const float*)d_in[5];
    const float* lscale   = (const float*)d_in[6];
    const float* btable   = (const float*)d_in[7];
    const int*   rpi      = (const int*)d_in[8];
    float* out = (float*)d_out;

    cudaFuncSetAttribute(attn_kernel, cudaFuncAttributeMaxDynamicSharedMemorySize,
                         ATTN_SMEM_BYTES);

    // 0) Precompute per-head rel-pos bias map
    bias_pre<<<128, 256>>>(btable, rpi);
    // 1) QKV projection: C[131072 x 768]
    {
        dim3 grid(QKV_N / 128, MROWS / 128);
        mma_gemm<true><<<grid, 128>>>(x, qkv_w, qkv_b, nullptr);
    }
    // 2) Attention per (window, head) — tensor cores, 3xTF32
    {
        attn_kernel<<<NWIN * HEADS, 128, ATTN_SMEM_BYTES>>>(mask, lscale);
    }
    // 3) Output projection: C[131072 x 256]
    {
        float* ao = nullptr;
        cudaGetSymbolAddress((void**)&ao, g_ao);
        dim3 grid(DIM / 128, MROWS / 128);
        mma_gemm<false><<<grid, 128>>>(ao, proj_w, proj_b, out);
    }
}

// round 5
// speedup vs baseline: 1.0908x; 1.0908x over previous
#include <cuda_runtime.h>
#include <cuda_bf16.h>
#include <cstdint>

#define NWIN   2048
#define WIN    64
#define DIM    256
#define HEADS  8
#define HD     32
#define QKV_N  768
#define MROWS  (NWIN*WIN)  // 131072

__device__ float g_q[(size_t)NWIN*HEADS*WIN*HD];
__device__ float g_k[(size_t)NWIN*HEADS*WIN*HD];
__device__ float g_v[(size_t)NWIN*HEADS*WIN*HD];
__device__ float g_ao[(size_t)NWIN*WIN*DIM];
__device__ float g_bm[(size_t)256*HEADS*WIN*WIN];  // bias+mask per (maskwin, head): 33.5MB

__device__ __forceinline__ unsigned f2tf32(float f) {
    unsigned r;
    asm("cvt.rna.tf32.f32 %0, %1;" : "=r"(r) : "f"(f));
    return r;
}

__device__ __forceinline__ void mma_tf32(float c[4],
                                         unsigned a0, unsigned a1, unsigned a2, unsigned a3,
                                         unsigned b0, unsigned b1) {
    asm volatile(
        "mma.sync.aligned.m16n8k8.row.col.f32.tf32.tf32.f32 "
        "{%0,%1,%2,%3}, {%4,%5,%6,%7}, {%8,%9}, {%0,%1,%2,%3};"
        : "+f"(c[0]), "+f"(c[1]), "+f"(c[2]), "+f"(c[3])
        : "r"(a0), "r"(a1), "r"(a2), "r"(a3), "r"(b0), "r"(b1));
}

// ---------------------------------------------------------------------------
// GEMM (round-3 proven version): C = A @ W^T + bias, K=256.
// Block 128x128, 4 warps (2m x 2n), warp 64x64, BK=32, single buffer.
// ---------------------------------------------------------------------------
#define SA 36

template<bool QKV>
__global__ void __launch_bounds__(128, 2) mma_gemm(const float* __restrict__ A,
                                                   const float* __restrict__ W,
                                                   const float* __restrict__ bias,
                                                   float* __restrict__ out)
{
    const int K = DIM;
    __shared__ unsigned As[128 * SA];
    __shared__ unsigned Bs[128 * SA];

    const int rowBase = blockIdx.y * 128;
    const int colBase = blockIdx.x * 128;
    const int tid  = threadIdx.x;
    const int lane = tid & 31;
    const int warp = tid >> 5;
    const int warpM = warp >> 1;
    const int warpN = warp & 1;
    const int g  = lane >> 2;
    const int tg = lane & 3;
    const int m0 = warpM * 64;
    const int n0 = warpN * 64;

    float acc[4][8][4] = {};

    for (int kb = 0; kb < K; kb += 32) {
        #pragma unroll
        for (int i = 0; i < 8; i++) {
            const int idx = tid + 128 * i;
            const int r = idx >> 3, c4 = idx & 7;
            float4 v = *(const float4*)&A[(size_t)(rowBase + r) * K + kb + c4 * 4];
            uint4 u = make_uint4(f2tf32(v.x), f2tf32(v.y), f2tf32(v.z), f2tf32(v.w));
            *(uint4*)&As[r * SA + c4 * 4] = u;
            float4 w = *(const float4*)&W[(size_t)(colBase + r) * K + kb + c4 * 4];
            uint4 uw = make_uint4(f2tf32(w.x), f2tf32(w.y), f2tf32(w.z), f2tf32(w.w));
            *(uint4*)&Bs[r * SA + c4 * 4] = uw;
        }
        __syncthreads();

        #pragma unroll
        for (int ks = 0; ks < 4; ks++) {
            const int k0 = ks * 8;
            unsigned a[4][4];
            #pragma unroll
            for (int am = 0; am < 4; am++) {
                const int mr = m0 + am * 16;
                a[am][0] = As[(mr + g)     * SA + k0 + tg];
                a[am][1] = As[(mr + g + 8) * SA + k0 + tg];
                a[am][2] = As[(mr + g)     * SA + k0 + tg + 4];
                a[am][3] = As[(mr + g + 8) * SA + k0 + tg + 4];
            }
            unsigned bf[8][2];
            #pragma unroll
            for (int an = 0; an < 8; an++) {
                const int nr = n0 + an * 8;
                bf[an][0] = Bs[(nr + g) * SA + k0 + tg];
                bf[an][1] = Bs[(nr + g) * SA + k0 + tg + 4];
            }
            #pragma unroll
            for (int am = 0; am < 4; am++)
                #pragma unroll
                for (int an = 0; an < 8; an++)
                    mma_tf32(acc[am][an], a[am][0], a[am][1], a[am][2], a[am][3],
                             bf[an][0], bf[an][1]);
        }
        __syncthreads();
    }

    #pragma unroll
    for (int am = 0; am < 4; am++) {
        #pragma unroll
        for (int an = 0; an < 8; an++) {
            const int col = colBase + n0 + an * 8 + 2 * tg;
            const float bi0 = bias[col], bi1 = bias[col + 1];
            #pragma unroll
            for (int half = 0; half < 2; half++) {
                const int row = rowBase + m0 + am * 16 + g + 8 * half;
                float2 v;
                v.x = acc[am][an][2 * half]     + bi0;
                v.y = acc[am][an][2 * half + 1] + bi1;
                if (QKV) {
                    const int b = row >> 6, n = row & 63;
                    const int which = col >> 8;
                    const int h = (col >> 5) & 7;
                    const int d = col & 31;
                    float* dst = (which == 0) ? g_q : (which == 1) ? g_k : g_v;
                    *(float2*)&dst[((((size_t)b * HEADS + h) * WIN) + n) * HD + d] = v;
                } else {
                    *(float2*)&out[(size_t)row * DIM + col] = v;
                }
            }
        }
    }
}

// ---------------------------------------------------------------------------
// Precompute combined bias+mask: g_bm[((w*8)+h)*4096 + e]
//   = bias_table[rpi[e]*8 + h] + mask[w*4096 + e]
// ---------------------------------------------------------------------------
__global__ void bm_pre(const float* __restrict__ bt, const int* __restrict__ rpi,
                       const float* __restrict__ mask)
{
    const int idx = blockIdx.x * 256 + threadIdx.x;   // 0 .. 8388607
    const int e = idx & 4095;
    const int h = (idx >> 12) & 7;
    const int w = idx >> 15;
    g_bm[idx] = bt[rpi[e] * HEADS + h] + mask[w * 4096 + e];
}

// ---------------------------------------------------------------------------
// Attention with 3xTF32 tensor-core MMA. One block per (window,head), 128 thr.
// ---------------------------------------------------------------------------
#define AP 36
#define VP 40
#define PP 68
#define SQH 0
#define SQL 2304
#define SKH 4608
#define SKL 6912
#define SVH 9216
#define SVL 11776
#define SAT 0        // alias over qh+ql (4352 <= 4608): bm staging, then P-hi
#define SPL 4608     // alias over kh+kl (4352 <= 4608): P-lo
#define ATTN_SMEM_FLOATS 14336
#define ATTN_SMEM_BYTES  (ATTN_SMEM_FLOATS * 4)

__device__ __forceinline__ unsigned fbits(float x) { return __float_as_uint(x); }

__global__ void __launch_bounds__(128) attn_kernel(const float* __restrict__ logit_scale)
{
    extern __shared__ float sm[];
    const int bh = blockIdx.x;
    const int b  = bh >> 3;
    const int h  = bh & 7;
    const int tid  = threadIdx.x;
    const int lane = tid & 31;
    const int warp = tid >> 5;
    const int g  = lane >> 2, tg = lane & 3;
    const int m0 = warp * 16;

    // Phase 0: load q,k,v fp32
    const size_t base = (size_t)bh * WIN * HD;
    #pragma unroll
    for (int i = 0; i < 4; i++) {
        const int idx = tid + 128 * i;
        const int n = idx >> 3, c = (idx & 7) * 4;
        *(float4*)&sm[SQH + n * AP + c] = *(const float4*)&g_q[base + n * HD + c];
        *(float4*)&sm[SKH + n * AP + c] = *(const float4*)&g_k[base + n * HD + c];
        *(float4*)&sm[SVH + n * VP + c] = *(const float4*)&g_v[base + n * HD + c];
    }
    __syncthreads();

    // Phase 1: normalize q (with scale) / k, tf32 hi/lo split; v hi/lo split
    {
        const float ls = __expf(fminf(logit_scale[h], 4.6051701859880914f));
        float* rowp = (tid < 64) ? &sm[SQH + tid * AP] : &sm[SKH + (tid - 64) * AP];
        float* lop  = (tid < 64) ? &sm[SQL + tid * AP] : &sm[SKL + (tid - 64) * AP];
        float s = 0.f;
        #pragma unroll
        for (int d = 0; d < HD; d++) s += rowp[d] * rowp[d];
        float inv = 1.0f / fmaxf(sqrtf(s), 1e-12f);
        if (tid < 64) inv *= ls;
        #pragma unroll
        for (int d = 0; d < HD; d++) {
            const float x = rowp[d] * inv;
            const float hf = __uint_as_float(f2tf32(x));
            rowp[d] = hf;
            lop[d] = __uint_as_float(f2tf32(x - hf));
        }
        #pragma unroll
        for (int j = 0; j < 16; j++) {
            const int e = tid * 16 + j;
            const int n = e >> 5, d = e & 31;
            const float x = sm[SVH + n * VP + d];
            const float hf = __uint_as_float(f2tf32(x));
            sm[SVH + n * VP + d] = hf;
            sm[SVL + n * VP + d] = __uint_as_float(f2tf32(x - hf));
        }
    }
    __syncthreads();

    // Phase 2: QK^T 3xTF32. warp -> rows m0..m0+15, 8 n-atoms, 4 k-atoms.
    float acc[8][4] = {};
    #pragma unroll
    for (int ka = 0; ka < 4; ka++) {
        const int k0 = ka * 8;
        unsigned ah[4], al[4];
        ah[0] = fbits(sm[SQH + (m0 + g)     * AP + k0 + tg]);
        ah[1] = fbits(sm[SQH + (m0 + g + 8) * AP + k0 + tg]);
        ah[2] = fbits(sm[SQH + (m0 + g)     * AP + k0 + tg + 4]);
        ah[3] = fbits(sm[SQH + (m0 + g + 8) * AP + k0 + tg + 4]);
        al[0] = fbits(sm[SQL + (m0 + g)     * AP + k0 + tg]);
        al[1] = fbits(sm[SQL + (m0 + g + 8) * AP + k0 + tg]);
        al[2] = fbits(sm[SQL + (m0 + g)     * AP + k0 + tg + 4]);
        al[3] = fbits(sm[SQL + (m0 + g + 8) * AP + k0 + tg + 4]);
        #pragma unroll
        for (int an = 0; an < 8; an++) {
            const int nr = an * 8;
            unsigned bh0 = fbits(sm[SKH + (nr + g) * AP + k0 + tg]);
            unsigned bh1 = fbits(sm[SKH + (nr + g) * AP + k0 + tg + 4]);
            unsigned bl0 = fbits(sm[SKL + (nr + g) * AP + k0 + tg]);
            unsigned bl1 = fbits(sm[SKL + (nr + g) * AP + k0 + tg + 4]);
            mma_tf32(acc[an], ah[0], ah[1], ah[2], ah[3], bh0, bh1);
            mma_tf32(acc[an], ah[0], ah[1], ah[2], ah[3], bl0, bl1);
            mma_tf32(acc[an], al[0], al[1], al[2], al[3], bh0, bh1);
        }
    }
    __syncthreads();   // all q/k smem reads done before bm staging overwrites

    // Phase 2b: stage combined bias+mask tile (coalesced) into SAT region
    {
        const float* bm = g_bm + ((size_t)((b & 255) * 8 + h) << 12);
        #pragma unroll
        for (int i = 0; i < 8; i++) {
            const int e = (tid + 128 * i) * 4;          // 0..4092
            float4 v = *(const float4*)&bm[e];
            *(float4*)&sm[SAT + (e >> 6) * PP + (e & 63)] = v;
        }
    }
    __syncthreads();

    // Phase 3: add bm (from smem) + softmax, all in registers
    const int r0 = m0 + g, r1 = r0 + 8;
    {
        float m0v = -1e30f, m1v = -1e30f;
        #pragma unroll
        for (int an = 0; an < 8; an++) {
            const int c = an * 8 + 2 * tg;
            float2 bm0 = *(const float2*)&sm[SAT + r0 * PP + c];
            float2 bm1 = *(const float2*)&sm[SAT + r1 * PP + c];
            acc[an][0] += bm0.x;
            acc[an][1] += bm0.y;
            acc[an][2] += bm1.x;
            acc[an][3] += bm1.y;
            m0v = fmaxf(m0v, fmaxf(acc[an][0], acc[an][1]));
            m1v = fmaxf(m1v, fmaxf(acc[an][2], acc[an][3]));
        }
        m0v = fmaxf(m0v, __shfl_xor_sync(0xffffffffu, m0v, 1));
        m0v = fmaxf(m0v, __shfl_xor_sync(0xffffffffu, m0v, 2));
        m1v = fmaxf(m1v, __shfl_xor_sync(0xffffffffu, m1v, 1));
        m1v = fmaxf(m1v, __shfl_xor_sync(0xffffffffu, m1v, 2));
        float s0 = 0.f, s1 = 0.f;
        #pragma unroll
        for (int an = 0; an < 8; an++) {
            acc[an][0] = __expf(acc[an][0] - m0v); s0 += acc[an][0];
            acc[an][1] = __expf(acc[an][1] - m0v); s0 += acc[an][1];
            acc[an][2] = __expf(acc[an][2] - m1v); s1 += acc[an][2];
            acc[an][3] = __expf(acc[an][3] - m1v); s1 += acc[an][3];
        }
        s0 += __shfl_xor_sync(0xffffffffu, s0, 1);
        s0 += __shfl_xor_sync(0xffffffffu, s0, 2);
        s1 += __shfl_xor_sync(0xffffffffu, s1, 1);
        s1 += __shfl_xor_sync(0xffffffffu, s1, 2);
        const float i0 = 1.0f / s0, i1 = 1.0f / s1;
        #pragma unroll
        for (int an = 0; an < 8; an++) {
            acc[an][0] *= i0; acc[an][1] *= i0;
            acc[an][2] *= i1; acc[an][3] *= i1;
        }
    }

    // Phase 4: store P hi/lo (warp writes only its own 16 rows)
    #pragma unroll
    for (int an = 0; an < 8; an++) {
        const int c = an * 8 + 2 * tg;
        #pragma unroll
        for (int q = 0; q < 4; q++) {
            const int rr = (q < 2) ? r0 : r1;
            const int cc = c + (q & 1);
            const float p = acc[an][q];
            const float hf = __uint_as_float(f2tf32(p));
            sm[SAT + rr * PP + cc] = hf;
            sm[SPL + rr * PP + cc] = __uint_as_float(f2tf32(p - hf));
        }
    }
    __syncwarp();

    // Phase 5: out = P @ V, 3xTF32. rows m0..+15, 4 n-atoms, 8 k-atoms.
    float oacc[4][4] = {};
    #pragma unroll
    for (int kj = 0; kj < 8; kj++) {
        const int k0 = kj * 8;
        unsigned ah[4], al[4];
        ah[0] = fbits(sm[SAT + (m0 + g)     * PP + k0 + tg]);
        ah[1] = fbits(sm[SAT + (m0 + g + 8) * PP + k0 + tg]);
        ah[2] = fbits(sm[SAT + (m0 + g)     * PP + k0 + tg + 4]);
        ah[3] = fbits(sm[SAT + (m0 + g + 8) * PP + k0 + tg + 4]);
        al[0] = fbits(sm[SPL + (m0 + g)     * PP + k0 + tg]);
        al[1] = fbits(sm[SPL + (m0 + g + 8) * PP + k0 + tg]);
        al[2] = fbits(sm[SPL + (m0 + g)     * PP + k0 + tg + 4]);
        al[3] = fbits(sm[SPL + (m0 + g + 8) * PP + k0 + tg + 4]);
        #pragma unroll
        for (int dn = 0; dn < 4; dn++) {
            const int nn = dn * 8;
            unsigned bh0 = fbits(sm[SVH + (k0 + tg)     * VP + nn + g]);
            unsigned bh1 = fbits(sm[SVH + (k0 + tg + 4) * VP + nn + g]);
            unsigned bl0 = fbits(sm[SVL + (k0 + tg)     * VP + nn + g]);
            unsigned bl1 = fbits(sm[SVL + (k0 + tg + 4) * VP + nn + g]);
            mma_tf32(oacc[dn], ah[0], ah[1], ah[2], ah[3], bh0, bh1);
            mma_tf32(oacc[dn], ah[0], ah[1], ah[2], ah[3], bl0, bl1);
            mma_tf32(oacc[dn], al[0], al[1], al[2], al[3], bh0, bh1);
        }
    }

    float* aop = g_ao + (size_t)b * WIN * DIM + h * HD;
    #pragma unroll
    for (int dn = 0; dn < 4; dn++) {
        const int c = dn * 8 + 2 * tg;
        float2 v0 = make_float2(oacc[dn][0], oacc[dn][1]);
        float2 v1 = make_float2(oacc[dn][2], oacc[dn][3]);
        *(float2*)&aop[(size_t)r0 * DIM + c] = v0;
        *(float2*)&aop[(size_t)r1 * DIM + c] = v1;
    }
}

// ---------------------------------------------------------------------------
extern "C" void kernel_launch(void* const* d_in, const int* in_sizes, int n_in,
                              void* d_out, int out_size)
{
    const float* x        = (const float*)d_in[0];
    const float* mask     = (const float*)d_in[1];
    const float* qkv_w    = (const float*)d_in[2];
    const float* qkv_b    = (const float*)d_in[3];
    const float* proj_w   = (const float*)d_in[4];
    const float* proj_b   = (const float*)d_in[5];
    const float* lscale   = (const float*)d_in[6];
    const float* btable   = (const float*)d_in[7];
    const int*   rpi      = (const int*)d_in[8];
    float* out = (float*)d_out;

    cudaFuncSetAttribute(attn_kernel, cudaFuncAttributeMaxDynamicSharedMemorySize,
                         ATTN_SMEM_BYTES);

    // 0) Precompute combined (bias+mask) tables: 256 maskwins x 8 heads
    bm_pre<<<32768, 256>>>(btable, rpi, mask);
    // 1) QKV projection
    {
        dim3 grid(QKV_N / 128, MROWS / 128);
        mma_gemm<true><<<grid, 128>>>(x, qkv_w, qkv_b, nullptr);
    }
    // 2) Attention per (window, head)
    {
        attn_kernel<<<NWIN * HEADS, 128, ATTN_SMEM_BYTES>>>(lscale);
    }
    // 3) Output projection
    {
        float* ao = nullptr;
        cudaGetSymbolAddress((void**)&ao, g_ao);
        dim3 grid(DIM / 128, MROWS / 128);
        mma_gemm<false><<<grid, 128>>>(ao, proj_w, proj_b, out);
    }
}